// round 16
// baseline (speedup 1.0000x reference)
#include <cuda_runtime.h>
#include <cuda_fp16.h>
#include <cstdint>

// Problem constants (fixed shapes)
#define Bn 32
#define Sn 1024
#define Hn 1024
#define Wn 128
#define Kn 6
#define NH 16
#define HD 64
#define MROWS (Bn * Wn * Kn)   // 24576
#define NCOLS (2 * Hn)         // 2048
#define NWIN (Bn * Wn)         // 4096

// Scratch: compacted fp16 A rows, fp16 W, compacted qk output, tables.
__device__ __half g_qkh[(size_t)MROWS * NCOLS];   // 100 MB
__device__ __half g_Ah[(size_t)MROWS * Hn];       // 50 MB (compacted gathered rows)
__device__ __half g_Wh[(size_t)NCOLS * Hn];       // 4 MB
__device__ int g_winStart[NWIN + 1];
__device__ long long g_srcOff2[MROWS];
__device__ __half g_biasH[NCOLS];

__device__ __forceinline__ uint32_t smem_u32(const void* p) {
    uint32_t a;
    asm("{ .reg .u64 t; cvta.to.shared.u64 t, %1; cvt.u32.u64 %0, t; }" : "=r"(a) : "l"(p));
    return a;
}
__device__ __forceinline__ void mma_f16(float& c0, float& c1, float& c2, float& c3,
                                        uint32_t a0, uint32_t a1, uint32_t a2, uint32_t a3,
                                        uint32_t b0, uint32_t b1)
{
    asm volatile(
        "mma.sync.aligned.m16n8k16.row.col.f32.f16.f16.f32 "
        "{%0,%1,%2,%3},{%4,%5,%6,%7},{%8,%9},{%0,%1,%2,%3};"
        : "+f"(c0), "+f"(c1), "+f"(c2), "+f"(c3)
        : "r"(a0), "r"(a1), "r"(a2), "r"(a3), "r"(b0), "r"(b1));
}
__device__ __forceinline__ void ldsm4(uint32_t& r0, uint32_t& r1, uint32_t& r2, uint32_t& r3,
                                      uint32_t addr)
{
    asm volatile("ldmatrix.sync.aligned.m8n8.x4.shared.b16 {%0,%1,%2,%3}, [%4];"
                 : "=r"(r0), "=r"(r1), "=r"(r2), "=r"(r3) : "r"(addr));
}
__device__ __forceinline__ void cpasync16(uint32_t dst, const void* src, uint32_t sz) {
    asm volatile("cp.async.cg.shared.global [%0], [%1], 16, %2;"
                 :: "r"(dst), "l"(src), "r"(sz) : "memory");
}
#define CP_COMMIT() asm volatile("cp.async.commit_group;" ::: "memory")
#define CP_WAIT(n)  asm volatile("cp.async.wait_group %0;" :: "n"(n) : "memory")
#define SW128(o) ((o) ^ (((o) >> 3) & 0x70))

// ---------------------------------------------------------------------------
// Kernel P: per-window active-length scan + compact gather table + bias->fp16.
// ---------------------------------------------------------------------------
__global__ __launch_bounds__(1024) void scan_kernel(
    const int* __restrict__ idx, const float* __restrict__ bias)
{
    __shared__ int part[1024];
    const int t = threadIdx.x;

    int myLen[4];
    int s = 0;
#pragma unroll
    for (int j = 0; j < 4; j++) {
        int w = t * 4 + j;
        int len = 1;                       // k=0 always active
#pragma unroll
        for (int k = 1; k < Kn; k++) len += (idx[w * Kn + k] != 0) ? 1 : 0;
        myLen[j] = len;
        s += len;
    }
    part[t] = s;
    __syncthreads();
    for (int off = 1; off < 1024; off <<= 1) {
        int v = (t >= off) ? part[t - off] : 0;
        __syncthreads();
        part[t] += v;
        __syncthreads();
    }
    int base = part[t] - s;                // exclusive prefix
#pragma unroll
    for (int j = 0; j < 4; j++) {
        int w = t * 4 + j;
        g_winStart[w] = base;
        int b = w >> 7;
        for (int k = 0; k < myLen[j]; k++) {
            int iv = idx[w * Kn + k];
            g_srcOff2[base + k] = (long long)(b * Sn + iv) * Hn;
        }
        base += myLen[j];
    }
    if (t == 1023) g_winStart[NWIN] = part[1023];

    for (int i = t; i < NCOLS; i += 1024) g_biasH[i] = __float2half(bias[i]);
}

// ---------------------------------------------------------------------------
// Kernel G: convert gathered A rows (compacted) AND W[0:2048] rows to fp16.
// Blocks [0, MROWS): A row conversion (exit if >= activeM).
// Blocks [MROWS, MROWS+2048): W conversion, 256 float4 per block.
// ---------------------------------------------------------------------------
__global__ __launch_bounds__(256) void conv_kernel(
    const float* __restrict__ TE, const float* __restrict__ Wt)
{
    const int g = blockIdx.x;
    const int t = threadIdx.x;
    if (g < MROWS) {
        if (g >= g_winStart[NWIN]) return;
        const float4 v = ((const float4*)(TE + g_srcOff2[g]))[t];
        __half2 h0 = __floats2half2_rn(v.x, v.y);
        __half2 h1 = __floats2half2_rn(v.z, v.w);
        uint2 hv;
        hv.x = *(uint32_t*)&h0;
        hv.y = *(uint32_t*)&h1;
        *(uint2*)(g_Ah + (size_t)g * Hn + t * 4) = hv;
    } else {
        size_t gid = (size_t)(g - MROWS) * 256 + t;   // float4 index over 2048*1024/4
        float4 v = ((const float4*)Wt)[gid];
        __half2 h0 = __floats2half2_rn(v.x, v.y);
        __half2 h1 = __floats2half2_rn(v.z, v.w);
        uint2 hv;
        hv.x = *(uint32_t*)&h0;
        hv.y = *(uint32_t*)&h1;
        *(uint2*)(g_Wh + gid * 4) = hv;
    }
}

// ---------------------------------------------------------------------------
// Kernel A: compacted FP16 tensor-core GEMM + fused copy/zero stream.
// grid (8, 256): y-blocks with rows < activeM run the GEMM (tile 128x256,
// BK=32, 4 stages, 512 threads, warp tile 32x64, mma.m16n8k16). All other
// CTAs stream the copy+zero of TE -> out (hidden under the compute-bound
// GEMM waves; the GEMM is at the mma.sync fp32-acc throughput floor).
// ---------------------------------------------------------------------------
#define STAGE_BYTES 24576
#define NSTAGE 4
#define GEMM_SMEM (2048 + NSTAGE * STAGE_BYTES)
#define GRIDY 256
#define COPY4 ((size_t)Bn * Sn * Hn / 4)   // 8388608 float4

__global__ __launch_bounds__(512, 1) void gemm_copy_f16(
    const float* __restrict__ bias,
    const float* __restrict__ TE,
    const int* __restrict__ idx,
    float* __restrict__ out)
{
    const int activeM = g_winStart[NWIN];
    const int nActiveBlk = (activeM + 127) >> 7;
    const int rowBase = blockIdx.y * 128;
    const int tid = threadIdx.x;

    if (blockIdx.y >= nActiveBlk) {
        // ---- copy + zero stream (no smem, no barrier) ----
        const int ncopy = (GRIDY - nActiveBlk) * 8;                 // >= 512
        const long long cid = (long long)(blockIdx.y - nActiveBlk) * 8 + blockIdx.x;
        for (size_t i = (size_t)cid * 512 + tid; i < COPY4; i += (size_t)ncopy * 512) {
            float4 v = ((const float4*)TE)[i];
            int row = (int)(i >> 8);          // H/4 = 256 float4 per row
            int b = row >> 10;
            int s = row & 1023;
            int w = s >> 3;
            int kk = s & 7;
            bool zero = false;
            if (kk < Kn) {
                int iv = idx[(b * Wn + w) * Kn + kk];
                zero = (kk == 0) || (iv != 0);
            }
            if (zero) v = make_float4(0.f, 0.f, 0.f, 0.f);
            ((float4*)out)[i] = v;
        }
        return;
    }

    extern __shared__ unsigned char sm[];
    float* biasSm = (float*)(sm + 1024);
    const uint32_t smBase = smem_u32(sm);
    const int colBase = blockIdx.x * 256;

    if (tid < 256) biasSm[tid] = bias[colBase + tid];
    __syncthreads();

    // ---- A loader: 4 threads/row, 16B each, contiguous compacted rows ----
    const int arow = tid >> 2;            // 0..127
    const int aq = tid & 3;
    const int ac = rowBase + arow;
    const __half* aSrc = g_Ah + (size_t)ac * Hn + aq * 8;   // halves
    const uint32_t aSz = (ac < activeM) ? 16u : 0u;
    const uint32_t aDst = smBase + 2048 + SW128((uint32_t)(arow * 64 + aq * 16));

    // ---- B loader: 2 threads/row, 32B each ----
    const int brow = tid >> 1;            // 0..255
    const int bh = tid & 1;
    const __half* bSrc = g_Wh + (size_t)(colBase + brow) * Hn + bh * 16;
    const uint32_t bDst0 = smBase + 2048 + 8192 + SW128((uint32_t)(brow * 64 + bh * 32));
    const uint32_t bDst1 = smBase + 2048 + 8192 + SW128((uint32_t)(brow * 64 + bh * 32 + 16));

    // ---- compute mapping: 16 warps = 4(m) x 4(n) ----
    const int wid = tid >> 5, lane = tid & 31;
    const int wr = wid >> 2, wc = wid & 3;
    const int g4 = lane >> 2, t4 = lane & 3;

    uint32_t aLd[2];
    {
        const int rowsel = (lane & 7) + ((lane >> 3) & 1) * 8;
        const uint32_t colHalf = (uint32_t)((lane >> 4) & 1) * 16u;
#pragma unroll
        for (int mi = 0; mi < 2; mi++) {
            uint32_t o = (uint32_t)((wr * 32 + mi * 16 + rowsel) * 64) + colHalf;
            aLd[mi] = smBase + 2048 + SW128(o);
        }
    }
    uint32_t bLd[4];
    {
        const int rowsel = (lane & 7) + ((lane >> 4) & 1) * 8;
        const uint32_t colHalf = (uint32_t)((lane >> 3) & 1) * 16u;
#pragma unroll
        for (int p = 0; p < 4; p++) {
            uint32_t o = (uint32_t)((wc * 64 + p * 16 + rowsel) * 64) + colHalf;
            bLd[p] = smBase + 2048 + 8192 + SW128(o);
        }
    }

    float acc[2][8][4];
#pragma unroll
    for (int mi = 0; mi < 2; mi++)
#pragma unroll
        for (int ni = 0; ni < 8; ni++)
#pragma unroll
            for (int q = 0; q < 4; q++) acc[mi][ni][q] = 0.f;

    // ---- prologue: prefetch stages 0..2 ----
#pragma unroll
    for (int s = 0; s < NSTAGE - 1; s++) {
        const uint32_t sb = (uint32_t)(s * STAGE_BYTES);
        const int k0 = s * 32;                         // halves
        cpasync16(aDst + sb, aSrc + k0, aSz);
        cpasync16(bDst0 + sb, bSrc + k0, 16u);
        cpasync16(bDst1 + sb, bSrc + k0 + 8, 16u);
        CP_COMMIT();
    }

    // ---- mainloop: 32 iterations of BK=32 (fp16) ----
    for (int it = 0; it < 32; ++it) {
        CP_WAIT(2);
        __syncthreads();

        if (it + NSTAGE - 1 < 32) {
            const uint32_t sb = (uint32_t)(((it + NSTAGE - 1) % NSTAGE) * STAGE_BYTES);
            const int k0 = (it + NSTAGE - 1) * 32;
            cpasync16(aDst + sb, aSrc + k0, aSz);
            cpasync16(bDst0 + sb, bSrc + k0, 16u);
            cpasync16(bDst1 + sb, bSrc + k0 + 8, 16u);
        }
        CP_COMMIT();

        const uint32_t sb = (uint32_t)((it % NSTAGE) * STAGE_BYTES);
#pragma unroll
        for (int ks = 0; ks < 2; ks++) {
            const uint32_t kx = (uint32_t)(ks * 32);
            uint32_t af[2][4];
#pragma unroll
            for (int mi = 0; mi < 2; mi++)
                ldsm4(af[mi][0], af[mi][1], af[mi][2], af[mi][3],
                      (aLd[mi] + sb) ^ kx);

            uint32_t bf[4][4];
#pragma unroll
            for (int p = 0; p < 4; p++)
                ldsm4(bf[p][0], bf[p][1], bf[p][2], bf[p][3],
                      (bLd[p] + sb) ^ kx);

#pragma unroll
            for (int p = 0; p < 4; p++)
#pragma unroll
                for (int h = 0; h < 2; h++) {
                    const int ni = 2 * p + h;
#pragma unroll
                    for (int mi = 0; mi < 2; mi++)
                        mma_f16(acc[mi][ni][0], acc[mi][ni][1], acc[mi][ni][2], acc[mi][ni][3],
                                af[mi][0], af[mi][1], af[mi][2], af[mi][3],
                                bf[p][2 * h], bf[p][2 * h + 1]);
                }
        }
    }

    // ---- epilogue: add bias, convert to fp16, store to g_qkh ----
#pragma unroll
    for (int mi = 0; mi < 2; mi++) {
        int row0 = rowBase + wr * 32 + mi * 16 + g4;
#pragma unroll
        for (int ni = 0; ni < 8; ni++) {
            int cl = wc * 64 + ni * 8 + t4 * 2;
            float b0 = biasSm[cl], b1 = biasSm[cl + 1];
            __half2 v0 = __floats2half2_rn(acc[mi][ni][0] + b0, acc[mi][ni][1] + b1);
            __half2 v1 = __floats2half2_rn(acc[mi][ni][2] + b0, acc[mi][ni][3] + b1);
            *(__half2*)&g_qkh[(size_t)row0 * NCOLS + colBase + cl] = v0;
            *(__half2*)&g_qkh[(size_t)(row0 + 8) * NCOLS + colBase + cl] = v1;
        }
    }
}

// ---------------------------------------------------------------------------
// Kernel C: per-window attention -> contrib -> unified, scatter to out.
// ---------------------------------------------------------------------------
#define QKSTRIDE_H (NCOLS + 16)   // 2064 halves = 4128 B per row

struct SmemB {
    __half qk[Kn][QKSTRIDE_H];    // ~24.2 KB
    float sc[NH][Kn][Kn];
    float wm[Kn][Kn];
    float contrib[8];
    float smask[8];
    int sidx[8];
    float sinv;
};

__global__ __launch_bounds__(256) void attn_merge_kernel(
    const float* __restrict__ TE,
    const int* __restrict__ idx,
    float* __restrict__ out)
{
    extern __shared__ unsigned char smraw[];
    SmemB* sm = reinterpret_cast<SmemB*>(smraw);

    const int tid = threadIdx.x;
    const int wg = blockIdx.x;     // window id = b*W + w
    const int b = wg >> 7;

    const int start = g_winStart[wg];
    const int len = g_winStart[wg + 1] - start;

    if (tid < Kn) {
        sm->sidx[tid] = idx[wg * Kn + tid];
        sm->smask[tid] = (tid < len) ? 1.f : 0.f;
    }

#pragma unroll
    for (int r = 0; r < Kn; r++) {
        const __half* srcR = (r < len) ? (g_qkh + (size_t)(start + r) * NCOLS)
                                       : g_biasH;
        ((uint4*)&sm->qk[r][0])[tid] = ((const uint4*)srcR)[tid];
    }
    __syncthreads();

    for (int t = tid; t < NH * Kn * Kn; t += 256) {
        int n = t / (Kn * Kn);
        int ij = t % (Kn * Kn);
        int i = ij / Kn, j = ij % Kn;
        const uint4* qp = (const uint4*)&sm->qk[i][n * HD];
        const uint4* kp = (const uint4*)&sm->qk[j][Hn + n * HD];
        float d = 0.f;
#pragma unroll
        for (int dd = 0; dd < HD / 8; dd++) {
            uint4 a = qp[dd];
            uint4 bb = kp[dd];
            const __half2* pa = (const __half2*)&a;
            const __half2* pb = (const __half2*)&bb;
#pragma unroll
            for (int jj = 0; jj < 4; jj++) {
                float2 fa = __half22float2(pa[jj]);
                float2 fb = __half22float2(pb[jj]);
                d += fa.x * fb.x + fa.y * fb.y;
            }
        }
        sm->sc[n][i][j] = d * 0.125f + sm->smask[i] * sm->smask[j];
    }
    __syncthreads();

    if (tid < NH * Kn) {
        int n = tid / Kn, i = tid % Kn;
        float* row = sm->sc[n][i];
        float mx = row[0];
#pragma unroll
        for (int j = 1; j < Kn; j++) mx = fmaxf(mx, row[j]);
        float e[Kn];
        float s = 0.f;
#pragma unroll
        for (int j = 0; j < Kn; j++) { e[j] = __expf(row[j] - mx); s += e[j]; }
        float inv = 1.f / s;
#pragma unroll
        for (int j = 0; j < Kn; j++) row[j] = e[j] * inv;
    }
    __syncthreads();

    if (tid < Kn * Kn) {
        int i = tid / Kn, j = tid % Kn;
        float s = 0.f;
#pragma unroll
        for (int n = 0; n < NH; n++) s += sm->sc[n][i][j];
        sm->wm[i][j] = s * (1.f / NH);
    }
    __syncthreads();

    if (tid < Kn) {
        int j = tid;
        float c = 0.f;
#pragma unroll
        for (int i = 0; i < Kn; i++)
            c += sm->smask[i] * sm->smask[j] * sm->wm[i][j];
        sm->contrib[j] = c;
    }
    __syncthreads();
    if (tid == 0) {
        float s = 0.f;
#pragma unroll
        for (int j = 0; j < Kn; j++) s += sm->contrib[j];
        sm->sinv = 1.f / (s + 1e-8f);
    }
    __syncthreads();

    float c[Kn];
    float inv = sm->sinv;
#pragma unroll
    for (int kk = 0; kk < Kn; kk++) c[kk] = sm->contrib[kk] * inv;

    const float4* rows[Kn];
#pragma unroll
    for (int kk = 0; kk < Kn; kk++)
        rows[kk] = (const float4*)(TE + ((size_t)b * Sn + sm->sidx[kk]) * Hn);

    float4* orow = (float4*)(out + ((size_t)b * Sn + sm->sidx[0]) * Hn);
    {
        float4 a = make_float4(0.f, 0.f, 0.f, 0.f);
#pragma unroll
        for (int kk = 0; kk < Kn; kk++) {
            float4 v = rows[kk][tid];
            a.x += c[kk] * v.x;
            a.y += c[kk] * v.y;
            a.z += c[kk] * v.z;
            a.w += c[kk] * v.w;
        }
        orow[tid] = a;
    }
}

// ---------------------------------------------------------------------------
extern "C" void kernel_launch(void* const* d_in, const int* in_sizes, int n_in,
                              void* d_out, int out_size)
{
    const float* TE   = (const float*)d_in[0];   // (32,1024,1024) f32
    const float* Wt   = (const float*)d_in[1];   // (3072,1024) f32
    const float* bias = (const float*)d_in[2];   // (3072,) f32
    const int* idx    = (const int*)d_in[3];     // (32,128,6) i32
    float* out = (float*)d_out;

    // Kernel P: window scan + compact gather table + bias fp16
    scan_kernel<<<1, 1024>>>(idx, bias);

    // Kernel G: gathered-A-row conversion (compacted) + W conversion
    conv_kernel<<<MROWS + 2048, 256>>>(TE, Wt);

    // Kernel A: fp16 tensor-core GEMM with fused copy+zero stream
    {
        static bool attr_set = false;
        if (!attr_set) {
            cudaFuncSetAttribute(gemm_copy_f16,
                                 cudaFuncAttributeMaxDynamicSharedMemorySize,
                                 GEMM_SMEM);
            attr_set = true;
        }
        dim3 grid(NCOLS / 256, GRIDY);   // (8, 256)
        gemm_copy_f16<<<grid, 512, GEMM_SMEM>>>(bias, TE, idx, out);
    }

    // Kernel C: attention + unified scatter (needs out + g_qkh + winStart)
    {
        static bool attr_set2 = false;
        if (!attr_set2) {
            cudaFuncSetAttribute(attn_merge_kernel,
                                 cudaFuncAttributeMaxDynamicSharedMemorySize,
                                 (int)sizeof(SmemB));
            attr_set2 = true;
        }
        attn_merge_kernel<<<NWIN, 256, sizeof(SmemB)>>>(TE, idx, out);
    }
}

// round 17
// speedup vs baseline: 1.1526x; 1.1526x over previous
#include <cuda_runtime.h>
#include <cuda_fp16.h>
#include <cstdint>

// Problem constants (fixed shapes)
#define Bn 32
#define Sn 1024
#define Hn 1024
#define Wn 128
#define Kn 6
#define NH 16
#define HD 64
#define MROWS (Bn * Wn * Kn)   // 24576
#define NCOLS (2 * Hn)         // 2048
#define NWIN (Bn * Wn)         // 4096

// Scratch: compacted fp16 A rows, fp16 W, compacted qk output, tables.
__device__ __half g_qkh[(size_t)MROWS * NCOLS];   // 100 MB
__device__ __half g_Ah[(size_t)MROWS * Hn];       // 50 MB (compacted gathered rows)
__device__ __half g_Wh[(size_t)NCOLS * Hn];       // 4 MB
__device__ int g_winStart[NWIN + 1];
__device__ long long g_srcOff2[MROWS];
__device__ __half g_biasH[NCOLS];

__device__ __forceinline__ uint32_t smem_u32(const void* p) {
    uint32_t a;
    asm("{ .reg .u64 t; cvta.to.shared.u64 t, %1; cvt.u32.u64 %0, t; }" : "=r"(a) : "l"(p));
    return a;
}
__device__ __forceinline__ void mma_f16(float& c0, float& c1, float& c2, float& c3,
                                        uint32_t a0, uint32_t a1, uint32_t a2, uint32_t a3,
                                        uint32_t b0, uint32_t b1)
{
    asm volatile(
        "mma.sync.aligned.m16n8k16.row.col.f32.f16.f16.f32 "
        "{%0,%1,%2,%3},{%4,%5,%6,%7},{%8,%9},{%0,%1,%2,%3};"
        : "+f"(c0), "+f"(c1), "+f"(c2), "+f"(c3)
        : "r"(a0), "r"(a1), "r"(a2), "r"(a3), "r"(b0), "r"(b1));
}
__device__ __forceinline__ void ldsm4(uint32_t& r0, uint32_t& r1, uint32_t& r2, uint32_t& r3,
                                      uint32_t addr)
{
    asm volatile("ldmatrix.sync.aligned.m8n8.x4.shared.b16 {%0,%1,%2,%3}, [%4];"
                 : "=r"(r0), "=r"(r1), "=r"(r2), "=r"(r3) : "r"(addr));
}
__device__ __forceinline__ void cpasync16(uint32_t dst, const void* src, uint32_t sz) {
    asm volatile("cp.async.cg.shared.global [%0], [%1], 16, %2;"
                 :: "r"(dst), "l"(src), "r"(sz) : "memory");
}
#define CP_COMMIT() asm volatile("cp.async.commit_group;" ::: "memory")
#define CP_WAIT(n)  asm volatile("cp.async.wait_group %0;" :: "n"(n) : "memory")
#define SW128(o) ((o) ^ (((o) >> 3) & 0x70))

// ---------------------------------------------------------------------------
// Kernel P: per-window active-length scan + compact gather table + bias->fp16.
// ---------------------------------------------------------------------------
__global__ __launch_bounds__(1024) void scan_kernel(
    const int* __restrict__ idx, const float* __restrict__ bias)
{
    __shared__ int part[1024];
    const int t = threadIdx.x;

    int myLen[4];
    int s = 0;
#pragma unroll
    for (int j = 0; j < 4; j++) {
        int w = t * 4 + j;
        int len = 1;                       // k=0 always active
#pragma unroll
        for (int k = 1; k < Kn; k++) len += (idx[w * Kn + k] != 0) ? 1 : 0;
        myLen[j] = len;
        s += len;
    }
    part[t] = s;
    __syncthreads();
    for (int off = 1; off < 1024; off <<= 1) {
        int v = (t >= off) ? part[t - off] : 0;
        __syncthreads();
        part[t] += v;
        __syncthreads();
    }
    int base = part[t] - s;                // exclusive prefix
#pragma unroll
    for (int j = 0; j < 4; j++) {
        int w = t * 4 + j;
        g_winStart[w] = base;
        int b = w >> 7;
        for (int k = 0; k < myLen[j]; k++) {
            int iv = idx[w * Kn + k];
            g_srcOff2[base + k] = (long long)(b * Sn + iv) * Hn;
        }
        base += myLen[j];
    }
    if (t == 1023) g_winStart[NWIN] = part[1023];

    for (int i = t; i < NCOLS; i += 1024) g_biasH[i] = __float2half(bias[i]);
}

// ---------------------------------------------------------------------------
// Kernel G: convert gathered A rows (compacted) AND W[0:2048] rows to fp16.
// ---------------------------------------------------------------------------
__global__ __launch_bounds__(256) void conv_kernel(
    const float* __restrict__ TE, const float* __restrict__ Wt)
{
    const int g = blockIdx.x;
    const int t = threadIdx.x;
    if (g < MROWS) {
        if (g >= g_winStart[NWIN]) return;
        const float4 v = ((const float4*)(TE + g_srcOff2[g]))[t];
        __half2 h0 = __floats2half2_rn(v.x, v.y);
        __half2 h1 = __floats2half2_rn(v.z, v.w);
        uint2 hv;
        hv.x = *(uint32_t*)&h0;
        hv.y = *(uint32_t*)&h1;
        *(uint2*)(g_Ah + (size_t)g * Hn + t * 4) = hv;
    } else {
        size_t gid = (size_t)(g - MROWS) * 256 + t;   // float4 over 2048*1024/4
        float4 v = ((const float4*)Wt)[gid];
        __half2 h0 = __floats2half2_rn(v.x, v.y);
        __half2 h1 = __floats2half2_rn(v.z, v.w);
        uint2 hv;
        hv.x = *(uint32_t*)&h0;
        hv.y = *(uint32_t*)&h1;
        *(uint2*)(g_Wh + gid * 4) = hv;
    }
}

// ---------------------------------------------------------------------------
// Kernel A: compacted FP16 tensor-core GEMM (standalone, R15 structure).
// Tile 128x256, BK=32, 4 stages of 24KB, 32 iters, 512 threads (16 warps,
// 4m x 4n), warp tile 32x64 via mma.m16n8k16. A rows contiguous from g_Ah.
// ---------------------------------------------------------------------------
#define STAGE_BYTES 24576
#define NSTAGE 4
#define GEMM_SMEM (2048 + NSTAGE * STAGE_BYTES)

__global__ __launch_bounds__(512, 1) void gemm_qk_f16(
    const float* __restrict__ bias)
{
    const int activeM = g_winStart[NWIN];
    const int rowBase = blockIdx.y * 128;
    if (rowBase >= activeM) return;

    extern __shared__ unsigned char sm[];
    float* biasSm = (float*)(sm + 1024);
    const uint32_t smBase = smem_u32(sm);

    const int tid = threadIdx.x;
    const int colBase = blockIdx.x * 256;

    if (tid < 256) biasSm[tid] = bias[colBase + tid];
    __syncthreads();

    // ---- A loader: 4 threads/row, 16B each, contiguous compacted rows ----
    const int arow = tid >> 2;            // 0..127
    const int aq = tid & 3;
    const int ac = rowBase + arow;
    const __half* aSrc = g_Ah + (size_t)ac * Hn + aq * 8;   // halves
    const uint32_t aSz = (ac < activeM) ? 16u : 0u;
    const uint32_t aDst = smBase + 2048 + SW128((uint32_t)(arow * 64 + aq * 16));

    // ---- B loader: 2 threads/row, 32B each ----
    const int brow = tid >> 1;            // 0..255
    const int bh = tid & 1;
    const __half* bSrc = g_Wh + (size_t)(colBase + brow) * Hn + bh * 16;
    const uint32_t bDst0 = smBase + 2048 + 8192 + SW128((uint32_t)(brow * 64 + bh * 32));
    const uint32_t bDst1 = smBase + 2048 + 8192 + SW128((uint32_t)(brow * 64 + bh * 32 + 16));

    // ---- compute mapping: 16 warps = 4(m) x 4(n) ----
    const int wid = tid >> 5, lane = tid & 31;
    const int wr = wid >> 2, wc = wid & 3;
    const int g4 = lane >> 2, t4 = lane & 3;

    uint32_t aLd[2];
    {
        const int rowsel = (lane & 7) + ((lane >> 3) & 1) * 8;
        const uint32_t colHalf = (uint32_t)((lane >> 4) & 1) * 16u;
#pragma unroll
        for (int mi = 0; mi < 2; mi++) {
            uint32_t o = (uint32_t)((wr * 32 + mi * 16 + rowsel) * 64) + colHalf;
            aLd[mi] = smBase + 2048 + SW128(o);
        }
    }
    uint32_t bLd[4];
    {
        const int rowsel = (lane & 7) + ((lane >> 4) & 1) * 8;
        const uint32_t colHalf = (uint32_t)((lane >> 3) & 1) * 16u;
#pragma unroll
        for (int p = 0; p < 4; p++) {
            uint32_t o = (uint32_t)((wc * 64 + p * 16 + rowsel) * 64) + colHalf;
            bLd[p] = smBase + 2048 + 8192 + SW128(o);
        }
    }

    float acc[2][8][4];
#pragma unroll
    for (int mi = 0; mi < 2; mi++)
#pragma unroll
        for (int ni = 0; ni < 8; ni++)
#pragma unroll
            for (int q = 0; q < 4; q++) acc[mi][ni][q] = 0.f;

    // ---- prologue: prefetch stages 0..2 ----
#pragma unroll
    for (int s = 0; s < NSTAGE - 1; s++) {
        const uint32_t sb = (uint32_t)(s * STAGE_BYTES);
        const int k0 = s * 32;                         // halves
        cpasync16(aDst + sb, aSrc + k0, aSz);
        cpasync16(bDst0 + sb, bSrc + k0, 16u);
        cpasync16(bDst1 + sb, bSrc + k0 + 8, 16u);
        CP_COMMIT();
    }

    // ---- mainloop: 32 iterations of BK=32 (fp16) ----
    for (int it = 0; it < 32; ++it) {
        CP_WAIT(2);
        __syncthreads();

        if (it + NSTAGE - 1 < 32) {
            const uint32_t sb = (uint32_t)(((it + NSTAGE - 1) % NSTAGE) * STAGE_BYTES);
            const int k0 = (it + NSTAGE - 1) * 32;
            cpasync16(aDst + sb, aSrc + k0, aSz);
            cpasync16(bDst0 + sb, bSrc + k0, 16u);
            cpasync16(bDst1 + sb, bSrc + k0 + 8, 16u);
        }
        CP_COMMIT();

        const uint32_t sb = (uint32_t)((it % NSTAGE) * STAGE_BYTES);
#pragma unroll
        for (int ks = 0; ks < 2; ks++) {
            const uint32_t kx = (uint32_t)(ks * 32);
            uint32_t af[2][4];
#pragma unroll
            for (int mi = 0; mi < 2; mi++)
                ldsm4(af[mi][0], af[mi][1], af[mi][2], af[mi][3],
                      (aLd[mi] + sb) ^ kx);

            uint32_t bf[4][4];
#pragma unroll
            for (int p = 0; p < 4; p++)
                ldsm4(bf[p][0], bf[p][1], bf[p][2], bf[p][3],
                      (bLd[p] + sb) ^ kx);

#pragma unroll
            for (int p = 0; p < 4; p++)
#pragma unroll
                for (int h = 0; h < 2; h++) {
                    const int ni = 2 * p + h;
#pragma unroll
                    for (int mi = 0; mi < 2; mi++)
                        mma_f16(acc[mi][ni][0], acc[mi][ni][1], acc[mi][ni][2], acc[mi][ni][3],
                                af[mi][0], af[mi][1], af[mi][2], af[mi][3],
                                bf[p][2 * h], bf[p][2 * h + 1]);
                }
        }
    }

    // ---- epilogue: add bias, convert to fp16, store to g_qkh ----
#pragma unroll
    for (int mi = 0; mi < 2; mi++) {
        int row0 = rowBase + wr * 32 + mi * 16 + g4;
#pragma unroll
        for (int ni = 0; ni < 8; ni++) {
            int cl = wc * 64 + ni * 8 + t4 * 2;
            float b0 = biasSm[cl], b1 = biasSm[cl + 1];
            __half2 v0 = __floats2half2_rn(acc[mi][ni][0] + b0, acc[mi][ni][1] + b1);
            __half2 v1 = __floats2half2_rn(acc[mi][ni][2] + b0, acc[mi][ni][3] + b1);
            *(__half2*)&g_qkh[(size_t)row0 * NCOLS + colBase + cl] = v0;
            *(__half2*)&g_qkh[(size_t)(row0 + 8) * NCOLS + colBase + cl] = v1;
        }
    }
}

// ---------------------------------------------------------------------------
// Kernel C: per-window attention + fused copy/zero of the window's 8 output
// rows. Window wg=(b,w) owns out rows [8w, 8w+8): row 0 gets the unified
// vector (idx[w][0] == 8w always), rows 1..len-1 are zeroed (masked), rows
// len..7 are copied from TE. Covers every output element exactly once.
// ---------------------------------------------------------------------------
#define QKSTRIDE_H (NCOLS + 16)   // 2064 halves = 4128 B per row

struct SmemB {
    __half qk[Kn][QKSTRIDE_H];    // ~24.2 KB
    float sc[NH][Kn][Kn];
    float wm[Kn][Kn];
    float contrib[8];
    float smask[8];
    int sidx[8];
    float sinv;
};

__global__ __launch_bounds__(256) void attn_merge_kernel(
    const float* __restrict__ TE,
    const int* __restrict__ idx,
    float* __restrict__ out)
{
    extern __shared__ unsigned char smraw[];
    SmemB* sm = reinterpret_cast<SmemB*>(smraw);

    const int tid = threadIdx.x;
    const int wg = blockIdx.x;     // window id = b*W + w
    const int b = wg >> 7;
    const int w = wg & 127;

    const int start = g_winStart[wg];
    const int len = g_winStart[wg + 1] - start;

    if (tid < Kn) {
        sm->sidx[tid] = idx[wg * Kn + tid];
        sm->smask[tid] = (tid < len) ? 1.f : 0.f;
    }

    // Load 6 qk rows: compacted GEMM output for r<len, bias vector otherwise.
#pragma unroll
    for (int r = 0; r < Kn; r++) {
        const __half* srcR = (r < len) ? (g_qkh + (size_t)(start + r) * NCOLS)
                                       : g_biasH;
        ((uint4*)&sm->qk[r][0])[tid] = ((const uint4*)srcR)[tid];
    }

    // Fused copy/zero of this window's output rows 1..7 (row 0 written later
    // with the unified vector). Placed here to overlap with compute phases.
    {
        const size_t rowOff = ((size_t)b * Sn + w * 8) * Hn;
        const float4* tbase = (const float4*)(TE + rowOff);
        float4* obase = (float4*)(out + rowOff);
        const float4 z = make_float4(0.f, 0.f, 0.f, 0.f);
#pragma unroll
        for (int r = 1; r < 8; r++) {
            float4 v = (r < len) ? z : tbase[r * 256 + tid];
            obase[r * 256 + tid] = v;
        }
    }
    __syncthreads();

    // Scores: 16 heads x 6 x 6 = 576 dot(64) tasks (fp16 operands, f32 accum)
    for (int t = tid; t < NH * Kn * Kn; t += 256) {
        int n = t / (Kn * Kn);
        int ij = t % (Kn * Kn);
        int i = ij / Kn, j = ij % Kn;
        const uint4* qp = (const uint4*)&sm->qk[i][n * HD];
        const uint4* kp = (const uint4*)&sm->qk[j][Hn + n * HD];
        float d = 0.f;
#pragma unroll
        for (int dd = 0; dd < HD / 8; dd++) {
            uint4 a = qp[dd];
            uint4 bb = kp[dd];
            const __half2* pa = (const __half2*)&a;
            const __half2* pb = (const __half2*)&bb;
#pragma unroll
            for (int jj = 0; jj < 4; jj++) {
                float2 fa = __half22float2(pa[jj]);
                float2 fb = __half22float2(pb[jj]);
                d += fa.x * fb.x + fa.y * fb.y;
            }
        }
        sm->sc[n][i][j] = d * 0.125f + sm->smask[i] * sm->smask[j];
    }
    __syncthreads();

    if (tid < NH * Kn) {
        int n = tid / Kn, i = tid % Kn;
        float* row = sm->sc[n][i];
        float mx = row[0];
#pragma unroll
        for (int j = 1; j < Kn; j++) mx = fmaxf(mx, row[j]);
        float e[Kn];
        float s = 0.f;
#pragma unroll
        for (int j = 0; j < Kn; j++) { e[j] = __expf(row[j] - mx); s += e[j]; }
        float inv = 1.f / s;
#pragma unroll
        for (int j = 0; j < Kn; j++) row[j] = e[j] * inv;
    }
    __syncthreads();

    if (tid < Kn * Kn) {
        int i = tid / Kn, j = tid % Kn;
        float s = 0.f;
#pragma unroll
        for (int n = 0; n < NH; n++) s += sm->sc[n][i][j];
        sm->wm[i][j] = s * (1.f / NH);
    }
    __syncthreads();

    if (tid < Kn) {
        int j = tid;
        float c = 0.f;
#pragma unroll
        for (int i = 0; i < Kn; i++)
            c += sm->smask[i] * sm->smask[j] * sm->wm[i][j];
        sm->contrib[j] = c;
    }
    __syncthreads();
    if (tid == 0) {
        float s = 0.f;
#pragma unroll
        for (int j = 0; j < Kn; j++) s += sm->contrib[j];
        sm->sinv = 1.f / (s + 1e-8f);
    }
    __syncthreads();

    float c[Kn];
    float inv = sm->sinv;
#pragma unroll
    for (int kk = 0; kk < Kn; kk++) c[kk] = sm->contrib[kk] * inv;

    const float4* rows[Kn];
#pragma unroll
    for (int kk = 0; kk < Kn; kk++)
        rows[kk] = (const float4*)(TE + ((size_t)b * Sn + sm->sidx[kk]) * Hn);

    // Unified vector -> output row 8w (== sidx[0])
    float4* orow = (float4*)(out + ((size_t)b * Sn + w * 8) * Hn);
    {
        float4 a = make_float4(0.f, 0.f, 0.f, 0.f);
#pragma unroll
        for (int kk = 0; kk < Kn; kk++) {
            float4 v = rows[kk][tid];
            a.x += c[kk] * v.x;
            a.y += c[kk] * v.y;
            a.z += c[kk] * v.z;
            a.w += c[kk] * v.w;
        }
        orow[tid] = a;
    }
}

// ---------------------------------------------------------------------------
extern "C" void kernel_launch(void* const* d_in, const int* in_sizes, int n_in,
                              void* d_out, int out_size)
{
    const float* TE   = (const float*)d_in[0];   // (32,1024,1024) f32
    const float* Wt   = (const float*)d_in[1];   // (3072,1024) f32
    const float* bias = (const float*)d_in[2];   // (3072,) f32
    const int* idx    = (const int*)d_in[3];     // (32,128,6) i32
    float* out = (float*)d_out;

    // Kernel P: window scan + compact gather table + bias fp16
    scan_kernel<<<1, 1024>>>(idx, bias);

    // Kernel G: gathered-A-row conversion (compacted) + W conversion
    conv_kernel<<<MROWS + 2048, 256>>>(TE, Wt);

    // Kernel A: compacted fp16 tensor-core GEMM into g_qkh
    {
        static bool attr_set = false;
        if (!attr_set) {
            cudaFuncSetAttribute(gemm_qk_f16,
                                 cudaFuncAttributeMaxDynamicSharedMemorySize,
                                 GEMM_SMEM);
            attr_set = true;
        }
        dim3 grid(NCOLS / 256, MROWS / 128);   // (8, 192); tail blocks exit
        gemm_qk_f16<<<grid, 512, GEMM_SMEM>>>(bias);
    }

    // Kernel C: attention + fused copy/zero + unified scatter
    {
        static bool attr_set2 = false;
        if (!attr_set2) {
            cudaFuncSetAttribute(attn_merge_kernel,
                                 cudaFuncAttributeMaxDynamicSharedMemorySize,
                                 (int)sizeof(SmemB));
            attr_set2 = true;
        }
        attn_merge_kernel<<<NWIN, 256, sizeof(SmemB)>>>(TE, idx, out);
    }
}